// round 17
// baseline (speedup 1.0000x reference)
#include <cuda_runtime.h>
#include <math.h>

// fl(sqrt(2)) and fl(1.5/sqrt(2)) exactly as numpy computes them (double -> float32).
// KODD = fp32 product, used for the sqrt2 / odd-exponent branch:
//   reference: pow(sqrt2f, e) * APPROX  ==  2^((e-1)/2) * (sqrt2f * APPROXf)  (within ~2 ulp)
__device__ __forceinline__ float quant_one(float x, float z, float c, float L,
                                           float s, float ls, float low)
{
    const float SQRT2F  = (float)1.4142135623730951;
    const float APPROXF = (float)1.0606601717798212;   // 1.5/sqrt(2) rounded to fp32
    const float KODD    = SQRT2F * APPROXF;            // constant-folded fp32 product

    float ax = fabsf(x);
    // log2(|x|/s) = log2|x| - log2(s); reference's +1e-32 only matters at x==0,
    // where log2f(0) = -inf drives the same zero-flag path (sign(0)=0 anyway).
    float xl = log2f(ax) - ls;
    bool  rt2 = (c != 2.0f);                 // code_map is exactly 2.0f or sqrt2f
    if (rt2) xl += xl;                       // log base sqrt2 = 2 * log2
    float xi = rintf(xl);                    // round-half-even == jnp.round
    float c1 = fmaxf(xi - z, low);           // clamp(min=lower)
    float xc = fminf(c1 - L, -1.0f);         // clamp(max=-1)
    float e  = xc + L + z;                   // integer in [-7, 9] on all live paths

    int ei = (int)e;                         // exact for integral e; dead paths don't care
    float q;
    if (rt2) {
        int h = ei >> 1;                     // floor(e/2), arithmetic shift
        q = __int_as_float((h + 127) << 23); // 2^h  (exact)
        if (ei & 1) q *= KODD;               // odd e: 2^h * sqrt2 * approx_factor
    } else {
        q = __int_as_float((ei + 127) << 23);// 2^e  (exact, matches pow(2,e))
    }
    if (c1 <= low) q = 0.0f;                 // underflow -> exact 0
    return q * copysignf(s, x);              // q * sign(x) * scale (x==0 -> q==0)
}

// sm_100a 256-bit vector global load/store (PTX ISA 8.7+, sm_100a+ only).
// 32-byte alignment guaranteed: rows are 11008 floats = 44032 B (32 | 44032),
// harness allocations are 256B-aligned, and off strides in whole 32B units.
__device__ __forceinline__ void ldg_v8(const float* __restrict__ p, float v[8]) {
    asm volatile("ld.global.v8.f32 {%0,%1,%2,%3,%4,%5,%6,%7}, [%8];"
        : "=f"(v[0]), "=f"(v[1]), "=f"(v[2]), "=f"(v[3]),
          "=f"(v[4]), "=f"(v[5]), "=f"(v[6]), "=f"(v[7])
        : "l"(p) : "memory");
}
// Write-through v8 store: output stream bypasses L2 write-allocate, so no
// dirty-line writeback scheduling competes with the 4 read streams.
__device__ __forceinline__ void stg_v8_wt(float* p, const float v[8]) {
    asm volatile("st.global.wt.v8.f32 [%0], {%1,%2,%3,%4,%5,%6,%7,%8};"
        :: "l"(p),
           "f"(v[0]), "f"(v[1]), "f"(v[2]), "f"(v[3]),
           "f"(v[4]), "f"(v[5]), "f"(v[6]), "f"(v[7])
        : "memory");
}

// Session-final shape (triple-confirmed): single fused launch, 8 elems/thread
// via 256-bit v8 memory ops — 4 front-batched load INSTRUCTIONS per thread
// (MLP_p1=4) at 32B each; one-shot independent CTAs; warp-uniform row params;
// fastest at 52% occupancy (regs=48) — outstanding bytes/SM is the resource.
// R17's single variable: write-through on the v8 store (last untried cell of
// the search matrix; composes the best-device (v8) and best-total (stwt) cells).
__global__ void __launch_bounds__(256)
quant_kernel(const float* __restrict__ X,
             const float* __restrict__ Z,
             const float* __restrict__ C,
             const float* __restrict__ L,
             const float* __restrict__ scale,
             const float* __restrict__ asym,
             float*       __restrict__ O,
             int nvec8)
{
    const int COLSV8 = 11008 / 8;            // 1376 v8-chunks per row (32 | 1376)
    int idx = blockIdx.x * blockDim.x + threadIdx.x;
    if (idx >= nvec8) return;
    int row  = idx / COLSV8;                 // warp-uniform
    long off = (long)idx * 8;

    // Front-batch the 4 wide loads (4 instructions, 32B each) + 2 broadcast scalars.
    float x[8], z[8], c[8], l[8];
    ldg_v8(X + off, x);
    ldg_v8(Z + off, z);
    ldg_v8(C + off, c);
    ldg_v8(L + off, l);
    float s = __ldg(scale + row);
    float a = __ldg(asym  + row);

    float ls  = log2f(s);
    float low = fmaf(a, -0.5f, -1.0f);       // -1 - asym/2

    float o[8];
#pragma unroll
    for (int i = 0; i < 8; i++)
        o[i] = quant_one(x[i], z[i], c[i], l[i], s, ls, low);

    stg_v8_wt(O + off, o);
}

extern "C" void kernel_launch(void* const* d_in, const int* in_sizes, int n_in,
                              void* d_out, int out_size)
{
    // metadata order: x, scale, zero, code_map, level_map, asym_map
    const float* x     = (const float*)d_in[0];
    const float* scale = (const float*)d_in[1];
    const float* zero  = (const float*)d_in[2];
    const float* code  = (const float*)d_in[3];
    const float* level = (const float*)d_in[4];
    const float* asym  = (const float*)d_in[5];

    int nvec8  = out_size / 8;               // total elems / 8 (11008 % 8 == 0)
    int blocks = (nvec8 + 255) / 256;

    quant_kernel<<<blocks, 256>>>(x, zero, code, level,
                                  scale, asym, (float*)d_out, nvec8);
}